// round 11
// baseline (speedup 1.0000x reference)
#include <cuda_runtime.h>
#include <cuda_fp16.h>

// ---------------------------------------------------------------------------
// SparseNetwork2: 4096 -> 2048 -> 1024 -> 512 -> 2, FAN_IN=128, edges
// contiguous per target. Smem-tiled SpMM: each block stages the full source
// layer x batch-column-chunk in shared memory (fp16; LayerNorm+ReLU fused
// into the staging pass), then many targets reuse it.
// g_acts holds RAW pre-activations in fp32 (bias included); normalization is
// applied on read using stats from reduce_kernel.
// R10 fixes: out_kernel gamma/beta double-offset (OOB); __launch_bounds__ on
// 512-thread gathers + outer loop unroll 1 (launchability / reg pressure).
// ---------------------------------------------------------------------------

#define BATCH       512
#define INPUT_DIM   4096
#define TOTAL_NODES 7682
#define FAN_IN      128
#define LN_EPS      1e-5f
#define E_TOTAL     459008

__device__ float g_acts[(size_t)TOTAL_NODES * BATCH];   // raw preacts (fp32)
__device__ float g_mean[BATCH];
__device__ float g_rstd[BATCH];
__device__ int2  g_packed[E_TOTAL];                     // (src, weight-bits)

// ---- pack (src, weight) into one 8B record ---------------------------------
__global__ void pack_kernel(const int* __restrict__ esrc,
                            const float* __restrict__ w) {
    const int e = blockIdx.x * 256 + threadIdx.x;
    if (e < E_TOTAL) g_packed[e] = make_int2(esrc[e], __float_as_int(w[e]));
}

// ---- layer 1: source = x (fp32, no LN). C=16 cols, pad stride 20 halfs. ----
// grid (32 bchunks, 4 tchunks), 512 threads, smem 4096*20*2 = 160 KB.
__global__ void __launch_bounds__(512, 1)
gather_x_kernel(const float* __restrict__ x,
                const float* __restrict__ bias) {
    extern __shared__ __half sx[];                 // [4096][20]
    const int tid = threadIdx.x;
    const int b0  = blockIdx.x * 16;

    // stage x[b0..b0+15][:] transposed into smem (coalesced fp32 reads)
    for (int idx = tid; idx < INPUT_DIM * 16; idx += 512) {
        const int b = idx >> 12;                   // 0..15
        const int n = idx & 4095;
        sx[n * 20 + b] = __float2half_rn(x[(size_t)(b0 + b) * INPUT_DIM + n]);
    }
    __syncthreads();

    const int group = tid & 3;                     // 4 cols each
    const int tpar  = tid >> 2;                    // 128 targets in parallel
    #pragma unroll 1
    for (int ti = 0; ti < 4; ti++) {
        const int t = blockIdx.y * 512 + ti * 128 + tpar;   // 0..2047
        const int2* __restrict__ ep = g_packed + t * FAN_IN;
        float4 acc = make_float4(0.f, 0.f, 0.f, 0.f);
        #pragma unroll 8
        for (int k = 0; k < FAN_IN; k++) {
            const int2  p = __ldg(ep + k);
            const float w = __int_as_float(p.y);
            const uint2 u = *reinterpret_cast<const uint2*>(sx + p.x * 20 + group * 4);
            const float2 f0 = __half22float2(*reinterpret_cast<const __half2*>(&u.x));
            const float2 f1 = __half22float2(*reinterpret_cast<const __half2*>(&u.y));
            acc.x += w * f0.x; acc.y += w * f0.y;
            acc.z += w * f1.x; acc.w += w * f1.y;
        }
        const float bb = bias[t];                  // target node 4096+t
        acc.x += bb; acc.y += bb; acc.z += bb; acc.w += bb;
        *reinterpret_cast<float4*>(
            g_acts + (size_t)(4096 + t) * BATCH + b0 + group * 4) = acc;
    }
}

// ---- layers 2,3: source = raw fp32 preacts; LN+ReLU fused into staging. ----
// C=32 cols, pad stride 36 halfs. 512 threads, grid (16 bchunks, y tchunks).
template<int SRC_DIM, int ITERS>
__global__ void __launch_bounds__(512, 1)
gather_acts_kernel(const float* __restrict__ bias_t,   // + tgt offset
                   const float* __restrict__ gamma_s,  // + src offset
                   const float* __restrict__ beta_s,
                   int src_node0, int tgt_node0, int ebase) {
    extern __shared__ __half sa[];                 // [SRC_DIM][36]
    const int tid = threadIdx.x;
    const int b0  = blockIdx.x * 32;

    // stage + LayerNorm + ReLU (fp32 math, fp16 into smem)
    for (int idx = tid; idx < SRC_DIM * 16; idx += 512) {
        const int node = idx >> 4;
        const int c2   = (idx & 15) * 2;
        const float2 v = *reinterpret_cast<const float2*>(
            g_acts + (size_t)(src_node0 + node) * BATCH + b0 + c2);
        const float2 m = *reinterpret_cast<const float2*>(g_mean + b0 + c2);
        const float2 r = *reinterpret_cast<const float2*>(g_rstd + b0 + c2);
        const float g  = gamma_s[node];
        const float be = beta_s[node];
        const float f0 = fmaxf(g * (v.x - m.x) * r.x + be, 0.f);
        const float f1 = fmaxf(g * (v.y - m.y) * r.y + be, 0.f);
        *reinterpret_cast<__half2*>(sa + node * 36 + c2) = __floats2half2_rn(f0, f1);
    }
    __syncthreads();

    const int group = tid & 7;                     // 8 groups x 4 cols = 32
    const int tpar  = tid >> 3;                    // 64 targets in parallel
    #pragma unroll 1
    for (int ti = 0; ti < ITERS; ti++) {
        const int t = blockIdx.y * (ITERS * 64) + ti * 64 + tpar;
        const int2* __restrict__ ep = g_packed + ebase + t * FAN_IN;
        float4 acc = make_float4(0.f, 0.f, 0.f, 0.f);
        #pragma unroll 8
        for (int k = 0; k < FAN_IN; k++) {
            const int2  p = __ldg(ep + k);
            const int   s = p.x - src_node0;
            const float w = __int_as_float(p.y);
            const uint2 u = *reinterpret_cast<const uint2*>(sa + s * 36 + group * 4);
            const float2 f0 = __half22float2(*reinterpret_cast<const __half2*>(&u.x));
            const float2 f1 = __half22float2(*reinterpret_cast<const __half2*>(&u.y));
            acc.x += w * f0.x; acc.y += w * f0.y;
            acc.z += w * f1.x; acc.w += w * f1.y;
        }
        const float bb = bias_t[t];
        acc.x += bb; acc.y += bb; acc.z += bb; acc.w += bb;
        *reinterpret_cast<float4*>(
            g_acts + (size_t)(tgt_node0 + t) * BATCH + b0 + group * 4) = acc;
    }
}

// ---- per-batch-column mean / rstd over the layer's raw fp32 preacts --------
__global__ void reduce_kernel(int s_node, int dim) {
    const int tx = threadIdx.x & 7;
    const int ty = threadIdx.x >> 3;
    const int b  = blockIdx.x * 8 + tx;

    float sum = 0.f, sq = 0.f;
    for (int n = ty; n < dim; n += 32) {
        const float v = g_acts[(size_t)(s_node + n) * BATCH + b];
        sum += v;
        sq  += v * v;
    }
    __shared__ float ssum[32][8];
    __shared__ float ssq[32][8];
    ssum[ty][tx] = sum;
    ssq[ty][tx]  = sq;
    __syncthreads();
    if (ty == 0) {
        float tsum = 0.f, tsq = 0.f;
        #pragma unroll
        for (int j = 0; j < 32; j++) { tsum += ssum[j][tx]; tsq += ssq[j][tx]; }
        const float inv_dim = 1.0f / (float)dim;
        const float mean = tsum * inv_dim;
        const float var  = tsq * inv_dim - mean * mean;   // biased, as torch LN
        g_mean[b] = mean;
        g_rstd[b] = rsqrtf(var + LN_EPS);
    }
}

// ---- output layer: LN+ReLU on layer-3 preacts applied on read --------------
// gamma/beta passed UN-offset; hidden index = s - 4096 (s in [7168,7680)).
__global__ void out_kernel(const float* __restrict__ bias,
                           const float* __restrict__ gamma,
                           const float* __restrict__ beta,
                           float* __restrict__ out) {
    const int t  = threadIdx.x;
    const int o  = blockIdx.x;                     // 0 or 1
    const int b0 = t * 4;
    const int2* __restrict__ ep = g_packed + 458752 + o * FAN_IN;
    const float4 m = *reinterpret_cast<const float4*>(g_mean + b0);
    const float4 r = *reinterpret_cast<const float4*>(g_rstd + b0);
    float4 acc = make_float4(0.f, 0.f, 0.f, 0.f);
    #pragma unroll 8
    for (int k = 0; k < FAN_IN; k++) {
        const int2  p  = ep[k];
        const int   s  = p.x;                      // 7168..7679
        const float w  = __int_as_float(p.y);
        const float g  = gamma[s - 4096];          // 3072..3583  (in bounds)
        const float be = beta[s - 4096];
        const float4 v = *reinterpret_cast<const float4*>(
            g_acts + (size_t)s * BATCH + b0);
        acc.x += w * fmaxf(g * (v.x - m.x) * r.x + be, 0.f);
        acc.y += w * fmaxf(g * (v.y - m.y) * r.y + be, 0.f);
        acc.z += w * fmaxf(g * (v.z - m.z) * r.z + be, 0.f);
        acc.w += w * fmaxf(g * (v.w - m.w) * r.w + be, 0.f);
    }
    const float bb = bias[3584 + o];
    out[(b0 + 0) * 2 + o] = acc.x + bb;
    out[(b0 + 1) * 2 + o] = acc.y + bb;
    out[(b0 + 2) * 2 + o] = acc.z + bb;
    out[(b0 + 3) * 2 + o] = acc.w + bb;
}

extern "C" void kernel_launch(void* const* d_in, const int* in_sizes, int n_in,
                              void* d_out, int out_size) {
    const float* x      = (const float*)d_in[0];
    const float* weight = (const float*)d_in[1];
    const float* bias   = (const float*)d_in[2];
    const float* gamma  = (const float*)d_in[3];
    const float* beta   = (const float*)d_in[4];
    const int*   esrc   = (const int*)  d_in[5];
    float* out = (float*)d_out;

    // opt-in to >48KB dynamic smem (idempotent host-side attribute sets)
    cudaFuncSetAttribute(gather_x_kernel,
        cudaFuncAttributeMaxDynamicSharedMemorySize, 4096 * 20 * 2);
    cudaFuncSetAttribute(gather_acts_kernel<2048, 2>,
        cudaFuncAttributeMaxDynamicSharedMemorySize, 2048 * 36 * 2);
    cudaFuncSetAttribute(gather_acts_kernel<1024, 1>,
        cudaFuncAttributeMaxDynamicSharedMemorySize, 1024 * 36 * 2);

    pack_kernel<<<E_TOTAL / 256, 256>>>(esrc, weight);

    // layer 1: nodes [4096,6144), edges [0,262144), source = x
    gather_x_kernel<<<dim3(32, 4), 512, 4096 * 20 * 2>>>(x, bias);
    reduce_kernel<<<64, 256>>>(4096, 2048);

    // layer 2: nodes [6144,7168), edges [262144,393216), source = layer1
    gather_acts_kernel<2048, 2><<<dim3(16, 8), 512, 2048 * 36 * 2>>>(
        bias + 2048, gamma, beta, 4096, 6144, 262144);
    reduce_kernel<<<64, 256>>>(6144, 1024);

    // layer 3: nodes [7168,7680), edges [393216,458752), source = layer2
    gather_acts_kernel<1024, 1><<<dim3(16, 8), 512, 1024 * 36 * 2>>>(
        bias + 3072, gamma + 2048, beta + 2048, 6144, 7168, 393216);
    reduce_kernel<<<64, 256>>>(7168, 512);

    // output layer: nodes [7680,7682), edges [458752,459008)
    out_kernel<<<2, 128>>>(bias, gamma, beta, out);
}

// round 12
// speedup vs baseline: 1.6941x; 1.6941x over previous
#include <cuda_runtime.h>
#include <cuda_fp16.h>

// ---------------------------------------------------------------------------
// SparseNetwork2: 4096 -> 2048 -> 1024 -> 512 -> 2, FAN_IN=128, edges
// contiguous per target. Smem-tiled SpMM: each block stages the full source
// layer x batch-column-chunk in shared memory (fp16; LayerNorm+ReLU fused
// into the staging pass), then many targets reuse it. g_acts holds RAW fp32
// pre-activations (bias included); normalization applied on read.
// R12: 1024 threads/block (2x occupancy at same smem), int4 paired edge
// loads (half the LDGs), one-wave grids.
// ---------------------------------------------------------------------------

#define BATCH       512
#define INPUT_DIM   4096
#define TOTAL_NODES 7682
#define FAN_IN      128
#define LN_EPS      1e-5f
#define E_TOTAL     459008

__device__ float g_acts[(size_t)TOTAL_NODES * BATCH];   // raw preacts (fp32)
__device__ float g_mean[BATCH];
__device__ float g_rstd[BATCH];
__device__ int2  g_packed[E_TOTAL];                     // (src, weight-bits)

// ---- pack (src, weight) into one 8B record ---------------------------------
__global__ void pack_kernel(const int* __restrict__ esrc,
                            const float* __restrict__ w) {
    const int e = blockIdx.x * 256 + threadIdx.x;
    if (e < E_TOTAL) g_packed[e] = make_int2(esrc[e], __float_as_int(w[e]));
}

// ---- layer 1: source = x (fp32, no LN). C=16 cols, pad stride 20 halfs. ----
// grid (32 bchunks, 4 tchunks), 1024 threads, smem 4096*20*2 = 160 KB.
__global__ void __launch_bounds__(1024, 1)
gather_x_kernel(const float* __restrict__ x,
                const float* __restrict__ bias) {
    extern __shared__ __half sx[];                 // [4096][20]
    const int tid = threadIdx.x;
    const int b0  = blockIdx.x * 16;

    // stage x[b0..b0+15][:] transposed into smem (coalesced fp32 reads)
    for (int idx = tid; idx < INPUT_DIM * 16; idx += 1024) {
        const int b = idx >> 12;                   // 0..15
        const int n = idx & 4095;
        sx[n * 20 + b] = __float2half_rn(x[(size_t)(b0 + b) * INPUT_DIM + n]);
    }
    __syncthreads();

    const int group = tid & 3;                     // 4 cols each
    const int tpar  = tid >> 2;                    // 256 targets in parallel
    #pragma unroll 1
    for (int ti = 0; ti < 2; ti++) {
        const int t = blockIdx.y * 512 + ti * 256 + tpar;   // 0..2047
        const int4* __restrict__ ep =
            reinterpret_cast<const int4*>(g_packed + t * FAN_IN);
        float4 acc = make_float4(0.f, 0.f, 0.f, 0.f);
        #pragma unroll 4
        for (int kk = 0; kk < FAN_IN / 2; kk++) {
            const int4  q  = __ldg(ep + kk);       // two (src, w) records
            const float w0 = __int_as_float(q.y);
            const float w1 = __int_as_float(q.w);
            const uint2 u0 = *reinterpret_cast<const uint2*>(sx + q.x * 20 + group * 4);
            const uint2 u1 = *reinterpret_cast<const uint2*>(sx + q.z * 20 + group * 4);
            const float2 a0 = __half22float2(*reinterpret_cast<const __half2*>(&u0.x));
            const float2 a1 = __half22float2(*reinterpret_cast<const __half2*>(&u0.y));
            const float2 c0 = __half22float2(*reinterpret_cast<const __half2*>(&u1.x));
            const float2 c1 = __half22float2(*reinterpret_cast<const __half2*>(&u1.y));
            acc.x += w0 * a0.x; acc.y += w0 * a0.y;
            acc.z += w0 * a1.x; acc.w += w0 * a1.y;
            acc.x += w1 * c0.x; acc.y += w1 * c0.y;
            acc.z += w1 * c1.x; acc.w += w1 * c1.y;
        }
        const float bb = bias[t];                  // target node 4096+t
        acc.x += bb; acc.y += bb; acc.z += bb; acc.w += bb;
        *reinterpret_cast<float4*>(
            g_acts + (size_t)(4096 + t) * BATCH + b0 + group * 4) = acc;
    }
}

// ---- layers 2,3: source = raw fp32 preacts; LN+ReLU fused into staging. ----
// C=32 cols, pad stride 36 halfs. 1024 threads.
template<int SRC_DIM, int ITERS>
__global__ void __launch_bounds__(1024, 1)
gather_acts_kernel(const float* __restrict__ bias_t,   // + tgt offset
                   const float* __restrict__ gamma_s,  // + src offset
                   const float* __restrict__ beta_s,
                   int src_node0, int tgt_node0, int ebase) {
    extern __shared__ __half sa[];                 // [SRC_DIM][36]
    const int tid = threadIdx.x;
    const int b0  = blockIdx.x * 32;

    // stage + LayerNorm + ReLU (fp32 math, fp16 into smem)
    for (int idx = tid; idx < SRC_DIM * 16; idx += 1024) {
        const int node = idx >> 4;
        const int c2   = (idx & 15) * 2;
        const float2 v = *reinterpret_cast<const float2*>(
            g_acts + (size_t)(src_node0 + node) * BATCH + b0 + c2);
        const float2 m = *reinterpret_cast<const float2*>(g_mean + b0 + c2);
        const float2 r = *reinterpret_cast<const float2*>(g_rstd + b0 + c2);
        const float g  = gamma_s[node];
        const float be = beta_s[node];
        const float f0 = fmaxf(g * (v.x - m.x) * r.x + be, 0.f);
        const float f1 = fmaxf(g * (v.y - m.y) * r.y + be, 0.f);
        *reinterpret_cast<__half2*>(sa + node * 36 + c2) = __floats2half2_rn(f0, f1);
    }
    __syncthreads();

    const int group = tid & 7;                     // 8 groups x 4 cols = 32
    const int tpar  = tid >> 3;                    // 128 targets in parallel
    #pragma unroll 1
    for (int ti = 0; ti < ITERS; ti++) {
        const int t = blockIdx.y * (ITERS * 128) + ti * 128 + tpar;
        const int4* __restrict__ ep =
            reinterpret_cast<const int4*>(g_packed + ebase + t * FAN_IN);
        float4 acc = make_float4(0.f, 0.f, 0.f, 0.f);
        #pragma unroll 4
        for (int kk = 0; kk < FAN_IN / 2; kk++) {
            const int4  q  = __ldg(ep + kk);
            const int   s0 = q.x - src_node0;
            const int   s1 = q.z - src_node0;
            const float w0 = __int_as_float(q.y);
            const float w1 = __int_as_float(q.w);
            const uint2 u0 = *reinterpret_cast<const uint2*>(sa + s0 * 36 + group * 4);
            const uint2 u1 = *reinterpret_cast<const uint2*>(sa + s1 * 36 + group * 4);
            const float2 a0 = __half22float2(*reinterpret_cast<const __half2*>(&u0.x));
            const float2 a1 = __half22float2(*reinterpret_cast<const __half2*>(&u0.y));
            const float2 c0 = __half22float2(*reinterpret_cast<const __half2*>(&u1.x));
            const float2 c1 = __half22float2(*reinterpret_cast<const __half2*>(&u1.y));
            acc.x += w0 * a0.x; acc.y += w0 * a0.y;
            acc.z += w0 * a1.x; acc.w += w0 * a1.y;
            acc.x += w1 * c0.x; acc.y += w1 * c0.y;
            acc.z += w1 * c1.x; acc.w += w1 * c1.y;
        }
        const float bb = bias_t[t];
        acc.x += bb; acc.y += bb; acc.z += bb; acc.w += bb;
        *reinterpret_cast<float4*>(
            g_acts + (size_t)(tgt_node0 + t) * BATCH + b0 + group * 4) = acc;
    }
}

// ---- per-batch-column mean / rstd over the layer's raw fp32 preacts --------
__global__ void reduce_kernel(int s_node, int dim) {
    const int tx = threadIdx.x & 7;
    const int ty = threadIdx.x >> 3;
    const int b  = blockIdx.x * 8 + tx;

    float sum = 0.f, sq = 0.f;
    for (int n = ty; n < dim; n += 32) {
        const float v = g_acts[(size_t)(s_node + n) * BATCH + b];
        sum += v;
        sq  += v * v;
    }
    __shared__ float ssum[32][8];
    __shared__ float ssq[32][8];
    ssum[ty][tx] = sum;
    ssq[ty][tx]  = sq;
    __syncthreads();
    if (ty == 0) {
        float tsum = 0.f, tsq = 0.f;
        #pragma unroll
        for (int j = 0; j < 32; j++) { tsum += ssum[j][tx]; tsq += ssq[j][tx]; }
        const float inv_dim = 1.0f / (float)dim;
        const float mean = tsum * inv_dim;
        const float var  = tsq * inv_dim - mean * mean;   // biased, as torch LN
        g_mean[b] = mean;
        g_rstd[b] = rsqrtf(var + LN_EPS);
    }
}

// ---- output layer: LN+ReLU on layer-3 preacts applied on read --------------
__global__ void out_kernel(const float* __restrict__ bias,
                           const float* __restrict__ gamma,
                           const float* __restrict__ beta,
                           float* __restrict__ out) {
    const int t  = threadIdx.x;
    const int o  = blockIdx.x;                     // 0 or 1
    const int b0 = t * 4;
    const int2* __restrict__ ep = g_packed + 458752 + o * FAN_IN;
    const float4 m = *reinterpret_cast<const float4*>(g_mean + b0);
    const float4 r = *reinterpret_cast<const float4*>(g_rstd + b0);
    float4 acc = make_float4(0.f, 0.f, 0.f, 0.f);
    #pragma unroll 8
    for (int k = 0; k < FAN_IN; k++) {
        const int2  p  = ep[k];
        const int   s  = p.x;                      // 7168..7679
        const float w  = __int_as_float(p.y);
        const float g  = gamma[s - 4096];          // 3072..3583 (in bounds)
        const float be = beta[s - 4096];
        const float4 v = *reinterpret_cast<const float4*>(
            g_acts + (size_t)s * BATCH + b0);
        acc.x += w * fmaxf(g * (v.x - m.x) * r.x + be, 0.f);
        acc.y += w * fmaxf(g * (v.y - m.y) * r.y + be, 0.f);
        acc.z += w * fmaxf(g * (v.z - m.z) * r.z + be, 0.f);
        acc.w += w * fmaxf(g * (v.w - m.w) * r.w + be, 0.f);
    }
    const float bb = bias[3584 + o];
    out[(b0 + 0) * 2 + o] = acc.x + bb;
    out[(b0 + 1) * 2 + o] = acc.y + bb;
    out[(b0 + 2) * 2 + o] = acc.z + bb;
    out[(b0 + 3) * 2 + o] = acc.w + bb;
}

extern "C" void kernel_launch(void* const* d_in, const int* in_sizes, int n_in,
                              void* d_out, int out_size) {
    const float* x      = (const float*)d_in[0];
    const float* weight = (const float*)d_in[1];
    const float* bias   = (const float*)d_in[2];
    const float* gamma  = (const float*)d_in[3];
    const float* beta   = (const float*)d_in[4];
    const int*   esrc   = (const int*)  d_in[5];
    float* out = (float*)d_out;

    // opt-in to >48KB dynamic smem (idempotent host-side attribute sets)
    cudaFuncSetAttribute(gather_x_kernel,
        cudaFuncAttributeMaxDynamicSharedMemorySize, 4096 * 20 * 2);
    cudaFuncSetAttribute(gather_acts_kernel<2048, 1>,
        cudaFuncAttributeMaxDynamicSharedMemorySize, 2048 * 36 * 2);
    cudaFuncSetAttribute(gather_acts_kernel<1024, 1>,
        cudaFuncAttributeMaxDynamicSharedMemorySize, 1024 * 36 * 2);

    pack_kernel<<<E_TOTAL / 256, 256>>>(esrc, weight);

    // layer 1: nodes [4096,6144), edges [0,262144), source = x
    // grid (32 bchunks, 4 tchunks) x ITERS 2 -> 128 blocks, 1 wave
    gather_x_kernel<<<dim3(32, 4), 1024, 4096 * 20 * 2>>>(x, bias);
    reduce_kernel<<<64, 256>>>(4096, 2048);

    // layer 2: nodes [6144,7168), edges [262144,393216), source = layer1
    // grid (16 bchunks, 8 tchunks) -> 128 blocks
    gather_acts_kernel<2048, 1><<<dim3(16, 8), 1024, 2048 * 36 * 2>>>(
        bias + 2048, gamma, beta, 4096, 6144, 262144);
    reduce_kernel<<<64, 256>>>(6144, 1024);

    // layer 3: nodes [7168,7680), edges [393216,458752), source = layer2
    // grid (16 bchunks, 4 tchunks) -> 64 blocks
    gather_acts_kernel<1024, 1><<<dim3(16, 4), 1024, 1024 * 36 * 2>>>(
        bias + 3072, gamma + 2048, beta + 2048, 6144, 7168, 393216);
    reduce_kernel<<<64, 256>>>(7168, 512);

    // output layer: nodes [7680,7682), edges [458752,459008)
    out_kernel<<<2, 128>>>(bias, gamma, beta, out);
}

// round 13
// speedup vs baseline: 1.7305x; 1.0215x over previous
#include <cuda_runtime.h>
#include <cuda_fp16.h>

// ---------------------------------------------------------------------------
// SparseNetwork2: 4096 -> 2048 -> 1024 -> 512 -> 2, FAN_IN=128, edges
// contiguous per target. Smem-tiled SpMM, R13 layout: lane = (target-slot,
// colpair) so each warp-LDS.32 reads contiguous row segments -> minimal bank
// conflicts (layer3: zero by construction). All tiles exactly 128 KB.
// g_acts holds RAW fp32 preacts (bias included); LN+ReLU is fused into the
// staging pass (stats from reduce_kernel). One-wave grids of 128 blocks.
// ---------------------------------------------------------------------------

#define BATCH       512
#define INPUT_DIM   4096
#define TOTAL_NODES 7682
#define FAN_IN      128
#define LN_EPS      1e-5f
#define E_TOTAL     459008

__device__ float g_acts[(size_t)TOTAL_NODES * BATCH];   // raw preacts (fp32)
__device__ float g_mean[BATCH];
__device__ float g_rstd[BATCH];
__device__ int2  g_packed[E_TOTAL];                     // (src, weight-bits)

// ---- pack (src, weight) into one 8B record ---------------------------------
__global__ void pack_kernel(const int* __restrict__ esrc,
                            const float* __restrict__ w) {
    const int e = blockIdx.x * 256 + threadIdx.x;
    if (e < E_TOTAL) g_packed[e] = make_int2(esrc[e], __float_as_int(w[e]));
}

// ---- layer 1: source = x (fp32, no LN). C=16 cols, stride 16 halfs. --------
// smem 4096*16*2 = 128 KB. grid (32 bchunks, 4 tchunks), 1024 threads.
// lane: tsub = l>>3 (4 targets/warp), cp = l&7 (8 colpairs = 16 cols).
__global__ void __launch_bounds__(1024, 1)
gather_x_kernel(const float* __restrict__ x,
                const float* __restrict__ bias) {
    extern __shared__ __half sx[];                 // [4096][16]
    const int tid = threadIdx.x;
    const int b0  = blockIdx.x * 16;

    // stage: coalesced x reads (consecutive tid -> consecutive n, fixed c)
    #pragma unroll 4
    for (int idx = tid; idx < INPUT_DIM * 16; idx += 1024) {
        const int c = idx >> 12;                   // 0..15
        const int n = idx & 4095;
        sx[n * 16 + c] = __float2half_rn(x[(size_t)(b0 + c) * INPUT_DIM + n]);
    }
    __syncthreads();

    const int w    = tid >> 5;                     // warp 0..31
    const int l    = tid & 31;
    const int tsub = l >> 3;                       // 0..3
    const int cp   = l & 7;                        // colpair 0..7
    #pragma unroll 1
    for (int pass = 0; pass < 4; pass++) {
        const int t = blockIdx.y * 512 + pass * 128 + w * 4 + tsub;  // 0..2047
        const int4* __restrict__ ep =
            reinterpret_cast<const int4*>(g_packed + t * FAN_IN);
        float2 acc = make_float2(0.f, 0.f);
        #pragma unroll 8
        for (int kk = 0; kk < FAN_IN / 2; kk++) {
            const int4 q = __ldg(ep + kk);         // 2 edges, bcast in 8 lanes
            const float2 a0 = __half22float2(
                *reinterpret_cast<const __half2*>(sx + q.x * 16 + cp * 2));
            const float2 a1 = __half22float2(
                *reinterpret_cast<const __half2*>(sx + q.z * 16 + cp * 2));
            const float w0 = __int_as_float(q.y);
            const float w1 = __int_as_float(q.w);
            acc.x = fmaf(w0, a0.x, acc.x); acc.y = fmaf(w0, a0.y, acc.y);
            acc.x = fmaf(w1, a1.x, acc.x); acc.y = fmaf(w1, a1.y, acc.y);
        }
        const float bb = bias[t];                  // target node 4096+t
        acc.x += bb; acc.y += bb;
        *reinterpret_cast<float2*>(
            g_acts + (size_t)(4096 + t) * BATCH + b0 + cp * 2) = acc;
    }
}

// ---- layers 2,3: LN+ReLU fused into staging; lane = (tsub, colpair). -------
// CC cols/chunk, LPT = CC/2 lanes per target, TPW = 32/LPT targets per warp.
// smem = SRCN*CC*2 = 128 KB for all layers. 1024 threads.
template<int SRCN, int CC, int PASSES>
__global__ void __launch_bounds__(1024, 1)
gather_acts_kernel(const float* __restrict__ bias_t,   // + tgt offset
                   const float* __restrict__ gamma_s,  // + src offset
                   const float* __restrict__ beta_s,
                   int src_node0, int tgt_node0, int ebase) {
    extern __shared__ __half sa[];                 // [SRCN][CC]
    constexpr int LPT = CC / 2;                    // lanes per target
    constexpr int TPW = 32 / LPT;                  // targets per warp
    const int tid = threadIdx.x;
    const int b0  = blockIdx.x * CC;

    // stage + LN + ReLU (fp32 math, fp16 smem); conflict-free writes
    #pragma unroll 4
    for (int idx = tid; idx < SRCN * (CC / 2); idx += 1024) {
        const int n  = idx / (CC / 2);
        const int c2 = (idx % (CC / 2)) * 2;
        const float2 v = *reinterpret_cast<const float2*>(
            g_acts + (size_t)(src_node0 + n) * BATCH + b0 + c2);
        const float2 m = *reinterpret_cast<const float2*>(g_mean + b0 + c2);
        const float2 r = *reinterpret_cast<const float2*>(g_rstd + b0 + c2);
        const float g  = gamma_s[n];
        const float be = beta_s[n];
        const float f0 = fmaxf(g * (v.x - m.x) * r.x + be, 0.f);
        const float f1 = fmaxf(g * (v.y - m.y) * r.y + be, 0.f);
        *reinterpret_cast<__half2*>(sa + n * CC + c2) = __floats2half2_rn(f0, f1);
    }
    __syncthreads();

    const int w    = tid >> 5;
    const int l    = tid & 31;
    const int tsub = l / LPT;
    const int cp   = l % LPT;
    #pragma unroll 1
    for (int pass = 0; pass < PASSES; pass++) {
        const int t = blockIdx.y * (PASSES * 32 * TPW) + pass * (32 * TPW)
                    + w * TPW + tsub;
        const int4* __restrict__ ep =
            reinterpret_cast<const int4*>(g_packed + ebase + t * FAN_IN);
        float2 acc = make_float2(0.f, 0.f);
        #pragma unroll 8
        for (int kk = 0; kk < FAN_IN / 2; kk++) {
            const int4 q  = __ldg(ep + kk);
            const int  s0 = q.x - src_node0;
            const int  s1 = q.z - src_node0;
            const float2 a0 = __half22float2(
                *reinterpret_cast<const __half2*>(sa + s0 * CC + cp * 2));
            const float2 a1 = __half22float2(
                *reinterpret_cast<const __half2*>(sa + s1 * CC + cp * 2));
            const float w0 = __int_as_float(q.y);
            const float w1 = __int_as_float(q.w);
            acc.x = fmaf(w0, a0.x, acc.x); acc.y = fmaf(w0, a0.y, acc.y);
            acc.x = fmaf(w1, a1.x, acc.x); acc.y = fmaf(w1, a1.y, acc.y);
        }
        const float bb = bias_t[t];
        acc.x += bb; acc.y += bb;
        *reinterpret_cast<float2*>(
            g_acts + (size_t)(tgt_node0 + t) * BATCH + b0 + cp * 2) = acc;
    }
}

// ---- per-batch-column mean / rstd over the layer's raw fp32 preacts --------
__global__ void reduce_kernel(int s_node, int dim) {
    const int tx = threadIdx.x & 7;
    const int ty = threadIdx.x >> 3;
    const int b  = blockIdx.x * 8 + tx;

    float sum = 0.f, sq = 0.f;
    for (int n = ty; n < dim; n += 32) {
        const float v = g_acts[(size_t)(s_node + n) * BATCH + b];
        sum += v;
        sq  += v * v;
    }
    __shared__ float ssum[32][8];
    __shared__ float ssq[32][8];
    ssum[ty][tx] = sum;
    ssq[ty][tx]  = sq;
    __syncthreads();
    if (ty == 0) {
        float tsum = 0.f, tsq = 0.f;
        #pragma unroll
        for (int j = 0; j < 32; j++) { tsum += ssum[j][tx]; tsq += ssq[j][tx]; }
        const float inv_dim = 1.0f / (float)dim;
        const float mean = tsum * inv_dim;
        const float var  = tsq * inv_dim - mean * mean;   // biased, as torch LN
        g_mean[b] = mean;
        g_rstd[b] = rsqrtf(var + LN_EPS);
    }
}

// ---- output layer: LN+ReLU on layer-3 preacts applied on read --------------
__global__ void out_kernel(const float* __restrict__ bias,
                           const float* __restrict__ gamma,
                           const float* __restrict__ beta,
                           float* __restrict__ out) {
    const int t  = threadIdx.x;
    const int o  = blockIdx.x;                     // 0 or 1
    const int b0 = t * 4;
    const int2* __restrict__ ep = g_packed + 458752 + o * FAN_IN;
    const float4 m = *reinterpret_cast<const float4*>(g_mean + b0);
    const float4 r = *reinterpret_cast<const float4*>(g_rstd + b0);
    float4 acc = make_float4(0.f, 0.f, 0.f, 0.f);
    #pragma unroll 8
    for (int k = 0; k < FAN_IN; k++) {
        const int2  p  = ep[k];
        const int   s  = p.x;                      // 7168..7679
        const float w  = __int_as_float(p.y);
        const float g  = gamma[s - 4096];          // 3072..3583 (in bounds)
        const float be = beta[s - 4096];
        const float4 v = *reinterpret_cast<const float4*>(
            g_acts + (size_t)s * BATCH + b0);
        acc.x += w * fmaxf(g * (v.x - m.x) * r.x + be, 0.f);
        acc.y += w * fmaxf(g * (v.y - m.y) * r.y + be, 0.f);
        acc.z += w * fmaxf(g * (v.z - m.z) * r.z + be, 0.f);
        acc.w += w * fmaxf(g * (v.w - m.w) * r.w + be, 0.f);
    }
    const float bb = bias[3584 + o];
    out[(b0 + 0) * 2 + o] = acc.x + bb;
    out[(b0 + 1) * 2 + o] = acc.y + bb;
    out[(b0 + 2) * 2 + o] = acc.z + bb;
    out[(b0 + 3) * 2 + o] = acc.w + bb;
}

extern "C" void kernel_launch(void* const* d_in, const int* in_sizes, int n_in,
                              void* d_out, int out_size) {
    const float* x      = (const float*)d_in[0];
    const float* weight = (const float*)d_in[1];
    const float* bias   = (const float*)d_in[2];
    const float* gamma  = (const float*)d_in[3];
    const float* beta   = (const float*)d_in[4];
    const int*   esrc   = (const int*)  d_in[5];
    float* out = (float*)d_out;

    constexpr int SMEM = 128 * 1024;               // all tiles exactly 128 KB
    cudaFuncSetAttribute(gather_x_kernel,
        cudaFuncAttributeMaxDynamicSharedMemorySize, SMEM);
    cudaFuncSetAttribute(gather_acts_kernel<2048, 32, 2>,
        cudaFuncAttributeMaxDynamicSharedMemorySize, SMEM);
    cudaFuncSetAttribute(gather_acts_kernel<1024, 64, 1>,
        cudaFuncAttributeMaxDynamicSharedMemorySize, SMEM);

    pack_kernel<<<(E_TOTAL + 255) / 256, 256>>>(esrc, weight);

    // layer 1: nodes [4096,6144), edges [0,262144), source = x
    // C=16: grid (32 bchunks, 4 tchunks) = 128 blocks, 4 passes of 128 tgts
    gather_x_kernel<<<dim3(32, 4), 1024, SMEM>>>(x, bias);
    reduce_kernel<<<64, 256>>>(4096, 2048);

    // layer 2: nodes [6144,7168), edges [262144,393216)
    // C=32: grid (16 bchunks, 8 tchunks) = 128 blocks, 2 passes of 64 tgts
    gather_acts_kernel<2048, 32, 2><<<dim3(16, 8), 1024, SMEM>>>(
        bias + 2048, gamma, beta, 4096, 6144, 262144);
    reduce_kernel<<<64, 256>>>(6144, 1024);

    // layer 3: nodes [7168,7680), edges [393216,458752)
    // C=64: grid (8 bchunks, 16 tchunks) = 128 blocks, 1 pass of 32 tgts
    gather_acts_kernel<1024, 64, 1><<<dim3(8, 16), 1024, SMEM>>>(
        bias + 3072, gamma + 2048, beta + 2048, 6144, 7168, 393216);
    reduce_kernel<<<64, 256>>>(7168, 512);

    // output layer: nodes [7680,7682), edges [458752,459008)
    out_kernel<<<2, 128>>>(bias, gamma, beta, out);
}

// round 17
// speedup vs baseline: 2.1633x; 1.2501x over previous
#include <cuda_runtime.h>
#include <cuda_fp16.h>

// ---------------------------------------------------------------------------
// SparseNetwork2: layered sparse MLP 4096 -> 2048 -> 1024 -> 512 -> 2,
// FAN_IN=128, edges contiguous per target -> per-layer gather.
// R17 = R9 (proven 80.4us streaming gathers, fp16 acts) + LAZY LayerNorm:
// g_acts holds RAW preacts (bias included); LN+ReLU applied on READ in the
// next layer's gather (and in out_kernel), using stats from reduce_kernel.
// Deletes all norm kernels and removes one fp16 quantization per layer.
// ---------------------------------------------------------------------------

#define BATCH       512
#define INPUT_DIM   4096
#define TOTAL_NODES 7682
#define FAN_IN      128
#define LN_EPS      1e-5f

// 7.9 MB fp16 activation scratch (L2-resident). [0,4096): x. Rest: raw preacts.
__device__ __half g_acts[(size_t)TOTAL_NODES * BATCH];
__device__ float  g_mean[BATCH];
__device__ float  g_rstd[BATCH];

// ---- transpose x [B, INPUT_DIM] (fp32) -> g_acts[n*B + b] (fp16) ----------
__global__ void transpose_kernel(const float* __restrict__ x) {
    __shared__ float tile[32][33];
    const int n0 = blockIdx.x * 32;
    const int b0 = blockIdx.y * 32;
    const int tx = threadIdx.x, ty = threadIdx.y;
    #pragma unroll
    for (int i = ty; i < 32; i += 8)
        tile[i][tx] = x[(size_t)(b0 + i) * INPUT_DIM + (n0 + tx)];
    __syncthreads();
    #pragma unroll
    for (int i = ty; i < 32; i += 8)
        g_acts[(size_t)(n0 + i) * BATCH + (b0 + tx)] = __float2half_rn(tile[tx][i]);
}

// ---- layer 1 gather: source = x (no LN). One block per target node. -------
// R9-proven. Writes RAW preact (+bias) fp16.
__global__ void gather_kernel(const float* __restrict__ weight,
                              const int*   __restrict__ esrc,
                              const float* __restrict__ bias,
                              int s_node, int ebase) {
    __shared__ float sw[FAN_IN];
    __shared__ int   ss[FAN_IN];
    const int t    = threadIdx.x;
    const int base = ebase + blockIdx.x * FAN_IN;
    sw[t] = weight[base + t];
    ss[t] = esrc[base + t];
    __syncthreads();

    const int b0 = t * 4;
    float4 acc = make_float4(0.f, 0.f, 0.f, 0.f);
    #pragma unroll 16
    for (int k = 0; k < FAN_IN; k++) {
        const float wk = sw[k];
        const uint2 u = *reinterpret_cast<const uint2*>(
            g_acts + (size_t)ss[k] * BATCH + b0);
        const float2 f0 = __half22float2(*reinterpret_cast<const __half2*>(&u.x));
        const float2 f1 = __half22float2(*reinterpret_cast<const __half2*>(&u.y));
        acc.x = fmaf(wk, f0.x, acc.x);
        acc.y = fmaf(wk, f0.y, acc.y);
        acc.z = fmaf(wk, f1.x, acc.z);
        acc.w = fmaf(wk, f1.y, acc.w);
    }
    const int   node = s_node + blockIdx.x;
    const float bb   = bias[node - INPUT_DIM];
    acc.x += bb; acc.y += bb; acc.z += bb; acc.w += bb;

    uint2 o;
    *reinterpret_cast<__half2*>(&o.x) = __floats2half2_rn(acc.x, acc.y);
    *reinterpret_cast<__half2*>(&o.y) = __floats2half2_rn(acc.z, acc.w);
    *reinterpret_cast<uint2*>(g_acts + (size_t)node * BATCH + b0) = o;
}

// ---- layers 2,3 gather: LN+ReLU applied on read (lazy) ---------------------
// Source acts are RAW preacts; normalize with current g_mean/g_rstd and
// per-src gamma/beta (hidden index = s - 4096, full arrays -> no offset trap).
__global__ void gather_ln_kernel(const float* __restrict__ weight,
                                 const int*   __restrict__ esrc,
                                 const float* __restrict__ bias,
                                 const float* __restrict__ gamma,
                                 const float* __restrict__ beta,
                                 int s_node, int ebase) {
    __shared__ float sw[FAN_IN];
    __shared__ int   ss[FAN_IN];
    const int t    = threadIdx.x;
    const int base = ebase + blockIdx.x * FAN_IN;
    sw[t] = weight[base + t];
    ss[t] = esrc[base + t];
    __syncthreads();

    const int b0 = t * 4;
    const float4 m = *reinterpret_cast<const float4*>(g_mean + b0);
    const float4 r = *reinterpret_cast<const float4*>(g_rstd + b0);
    const float nm0 = -m.x * r.x, nm1 = -m.y * r.y;
    const float nm2 = -m.z * r.z, nm3 = -m.w * r.w;

    float4 acc = make_float4(0.f, 0.f, 0.f, 0.f);
    #pragma unroll 8
    for (int k = 0; k < FAN_IN; k++) {
        const int   s  = ss[k];
        const float wk = sw[k];
        const float gm = __ldg(gamma + s - 4096);   // warp-uniform broadcast
        const float be = __ldg(beta  + s - 4096);
        const uint2 u = *reinterpret_cast<const uint2*>(
            g_acts + (size_t)s * BATCH + b0);
        const float2 f0 = __half22float2(*reinterpret_cast<const __half2*>(&u.x));
        const float2 f1 = __half22float2(*reinterpret_cast<const __half2*>(&u.y));
        const float a0 = fmaxf(fmaf(fmaf(f0.x, r.x, nm0), gm, be), 0.f);
        const float a1 = fmaxf(fmaf(fmaf(f0.y, r.y, nm1), gm, be), 0.f);
        const float a2 = fmaxf(fmaf(fmaf(f1.x, r.z, nm2), gm, be), 0.f);
        const float a3 = fmaxf(fmaf(fmaf(f1.y, r.w, nm3), gm, be), 0.f);
        acc.x = fmaf(wk, a0, acc.x);
        acc.y = fmaf(wk, a1, acc.y);
        acc.z = fmaf(wk, a2, acc.z);
        acc.w = fmaf(wk, a3, acc.w);
    }
    const int   node = s_node + blockIdx.x;
    const float bb   = bias[node - INPUT_DIM];
    acc.x += bb; acc.y += bb; acc.z += bb; acc.w += bb;

    uint2 o;
    *reinterpret_cast<__half2*>(&o.x) = __floats2half2_rn(acc.x, acc.y);
    *reinterpret_cast<__half2*>(&o.y) = __floats2half2_rn(acc.z, acc.w);
    *reinterpret_cast<uint2*>(g_acts + (size_t)node * BATCH + b0) = o;
}

// ---- per-batch-column mean / rstd over the layer's RAW preacts -------------
// R9-proven. 64 blocks x 256 threads.
__global__ void reduce_kernel(int s_node, int dim) {
    const int tx = threadIdx.x & 7;    // batch column within block (0..7)
    const int ty = threadIdx.x >> 3;   // node stride group (0..31)
    const int b  = blockIdx.x * 8 + tx;

    float sum = 0.f, sq = 0.f;
    for (int n = ty; n < dim; n += 32) {
        const float v = __half2float(g_acts[(size_t)(s_node + n) * BATCH + b]);
        sum += v;
        sq  += v * v;
    }
    __shared__ float ssum[32][8];
    __shared__ float ssq[32][8];
    ssum[ty][tx] = sum;
    ssq[ty][tx]  = sq;
    __syncthreads();
    if (ty == 0) {
        float tsum = 0.f, tsq = 0.f;
        #pragma unroll
        for (int j = 0; j < 32; j++) { tsum += ssum[j][tx]; tsq += ssq[j][tx]; }
        const float inv_dim = 1.0f / (float)dim;
        const float mean = tsum * inv_dim;
        const float var  = tsq * inv_dim - mean * mean;  // biased, as torch LN
        g_mean[b] = mean;
        g_rstd[b] = rsqrtf(var + LN_EPS);
    }
}

// ---- output layer: lazy LN on layer-3 raw preacts, fp32 out ---------------
__global__ void out_kernel(const float* __restrict__ weight,
                           const int*   __restrict__ esrc,
                           const float* __restrict__ bias,
                           const float* __restrict__ gamma,
                           const float* __restrict__ beta,
                           float* __restrict__ out) {
    __shared__ float sw[FAN_IN];
    __shared__ int   ss[FAN_IN];
    const int t    = threadIdx.x;
    const int o    = blockIdx.x;             // 0 or 1
    const int base = 458752 + o * FAN_IN;
    sw[t] = weight[base + t];
    ss[t] = esrc[base + t];
    __syncthreads();

    const int b0 = t * 4;
    const float4 m = *reinterpret_cast<const float4*>(g_mean + b0);
    const float4 r = *reinterpret_cast<const float4*>(g_rstd + b0);
    const float nm0 = -m.x * r.x, nm1 = -m.y * r.y;
    const float nm2 = -m.z * r.z, nm3 = -m.w * r.w;

    float4 acc = make_float4(0.f, 0.f, 0.f, 0.f);
    #pragma unroll 8
    for (int k = 0; k < FAN_IN; k++) {
        const int   s  = ss[k];                  // 7168..7679
        const float wk = sw[k];
        const float gm = __ldg(gamma + s - 4096);   // 3072..3583 (in bounds)
        const float be = __ldg(beta  + s - 4096);
        const uint2 u = *reinterpret_cast<const uint2*>(
            g_acts + (size_t)s * BATCH + b0);
        const float2 f0 = __half22float2(*reinterpret_cast<const __half2*>(&u.x));
        const float2 f1 = __half22float2(*reinterpret_cast<const __half2*>(&u.y));
        acc.x = fmaf(wk, fmaxf(fmaf(fmaf(f0.x, r.x, nm0), gm, be), 0.f), acc.x);
        acc.y = fmaf(wk, fmaxf(fmaf(fmaf(f0.y, r.y, nm1), gm, be), 0.f), acc.y);
        acc.z = fmaf(wk, fmaxf(fmaf(fmaf(f1.x, r.z, nm2), gm, be), 0.f), acc.z);
        acc.w = fmaf(wk, fmaxf(fmaf(fmaf(f1.y, r.w, nm3), gm, be), 0.f), acc.w);
    }
    const float bb = bias[3584 + o];
    out[(b0 + 0) * 2 + o] = acc.x + bb;
    out[(b0 + 1) * 2 + o] = acc.y + bb;
    out[(b0 + 2) * 2 + o] = acc.z + bb;
    out[(b0 + 3) * 2 + o] = acc.w + bb;
}

extern "C" void kernel_launch(void* const* d_in, const int* in_sizes, int n_in,
                              void* d_out, int out_size) {
    const float* x      = (const float*)d_in[0];
    const float* weight = (const float*)d_in[1];
    const float* bias   = (const float*)d_in[2];
    const float* gamma  = (const float*)d_in[3];
    const float* beta   = (const float*)d_in[4];
    const int*   esrc   = (const int*)  d_in[5];
    // d_in[6] = edge_tgt: implied by contiguous per-target layout; unused.
    float* out = (float*)d_out;

    // x.T into fp16 activation scratch
    transpose_kernel<<<dim3(INPUT_DIM / 32, BATCH / 32), dim3(32, 8)>>>(x);

    // layer 1: nodes [4096,6144), edges [0,262144); source = x (no LN)
    gather_kernel<<<2048, 128>>>(weight, esrc, bias, 4096, 0);
    reduce_kernel<<<64, 256>>>(4096, 2048);     // layer-1 stats

    // layer 2: nodes [6144,7168), edges [262144,393216); lazy LN on layer-1
    gather_ln_kernel<<<1024, 128>>>(weight, esrc, bias, gamma, beta,
                                    6144, 262144);
    reduce_kernel<<<64, 256>>>(6144, 1024);     // layer-2 stats

    // layer 3: nodes [7168,7680), edges [393216,458752); lazy LN on layer-2
    gather_ln_kernel<<<512, 128>>>(weight, esrc, bias, gamma, beta,
                                   7168, 393216);
    reduce_kernel<<<64, 256>>>(7168, 512);      // layer-3 stats

    // output layer: edges [458752,459008); lazy LN on layer-3
    out_kernel<<<2, 128>>>(weight, esrc, bias, gamma, beta, out);
}